// round 3
// baseline (speedup 1.0000x reference)
#include <cuda_runtime.h>
#include <cuda_bf16.h>
#include <cstdint>

// Complex MAC: (sr,si) += (ar,ai) * (br,bi)
#define CMAC(sr, si, ar, ai, br, bi) do { \
  (sr) = fmaf((ar), (br), (sr)); (sr) = fmaf(-(ai), (bi), (sr)); \
  (si) = fmaf((ar), (bi), (si)); (si) = fmaf((ai), (br), (si)); } while (0)

constexpr int Bc = 4, Lc = 2048, Cc = 64;         // problem dims (R = 8)
constexpr int T = 64;                              // steps per chunk
constexpr int NCHUNK = Lc / T;                     // 32
constexpr int NSEQ = Bc * Cc;                      // 256
constexpr int NUNIT = NSEQ * NCHUNK;               // 8192

// Scratch: chunk transition matrices, chunk offsets, entering states.
__device__ float2 g_M2[NUNIT * 64];   // [unit][i*8+k] (row-major), 4 MB
__device__ float2 g_v2[NUNIT * 8];    // [unit][i]
__device__ float2 g_E2[NUNIT * 8];    // [unit][i] entering state

// ---------------------------------------------------------------------------
// Kernel 1: fold each chunk of T steps into (M, v):  s_out = M s_in + v.
// 8 threads per unit; thread j owns column j of M and element j of v.
// ---------------------------------------------------------------------------
__global__ __launch_bounds__(256, 2) void k_fold(
    const float* __restrict__ Are, const float* __restrict__ Aim,
    const float* __restrict__ Xre, const float* __restrict__ Xim)
{
  __shared__ float4 sA[32][32];   // per unit: 16 f4 of A_re, 16 f4 of A_im
  const int tid = threadIdx.x;
  const int u = tid >> 3, j = tid & 7;
  const int unit = blockIdx.x * 32 + u;
  const int seq = unit >> 5, chunk = unit & 31;
  const int b = seq >> 6, c = seq & 63;
  const int t0 = chunk * T;

  const float* arp = Are + (size_t)(b * Lc + t0) * 4096 + c * 64 + j * 8;
  const float* aip = Aim + (size_t)(b * Lc + t0) * 4096 + c * 64 + j * 8;
  const float* xrp = Xre + (size_t)(b * Lc + t0) * 512 + c * 8 + j;
  const float* xip = Xim + (size_t)(b * Lc + t0) * 512 + c * 8 + j;
  const float* sre = (const float*)&sA[u][0];
  const float* simp = (const float*)&sA[u][16];

  // Stage A(t0): lane j loads row j (coalesced per unit).
  sA[u][j * 2 + 0] = *(const float4*)(arp);
  sA[u][j * 2 + 1] = *(const float4*)(arp + 4);
  sA[u][16 + j * 2 + 0] = *(const float4*)(aip);
  sA[u][16 + j * 2 + 1] = *(const float4*)(aip + 4);
  float vr = xrp[0], vi = xip[0];          // v = X(t0)
  __syncwarp();

  // M = A(t0): column j.
  float cr[8], ci[8];
  #pragma unroll
  for (int k = 0; k < 8; k++) { cr[k] = sre[k * 8 + j]; ci[k] = simp[k * 8 + j]; }

  // Prefetch A,X(t0+1) into registers.
  arp += 4096; aip += 4096; xrp += 512; xip += 512;
  float4 nr0 = *(const float4*)(arp), nr1 = *(const float4*)(arp + 4);
  float4 ni0 = *(const float4*)(aip), ni1 = *(const float4*)(aip + 4);
  float nxr = xrp[0], nxi = xip[0];

  for (int s = 1; s < T; ++s) {
    __syncwarp();   // everyone done reading SMEM from previous step
    sA[u][j * 2 + 0] = nr0; sA[u][j * 2 + 1] = nr1;
    sA[u][16 + j * 2 + 0] = ni0; sA[u][16 + j * 2 + 1] = ni1;
    const float cxr = nxr, cxi = nxi;
    if (s < T - 1) {   // prefetch next step (hidden under compute below)
      arp += 4096; aip += 4096; xrp += 512; xip += 512;
      nr0 = *(const float4*)(arp); nr1 = *(const float4*)(arp + 4);
      ni0 = *(const float4*)(aip); ni1 = *(const float4*)(aip + 4);
      nxr = xrp[0]; nxi = xip[0];
    }
    __syncwarp();   // SMEM now holds A(t0+s)

    // Gather v across the unit (width-8 shuffles).
    float vor[8], voi[8];
    #pragma unroll
    for (int k = 0; k < 8; k++) {
      vor[k] = __shfl_sync(0xffffffffu, vr, k, 8);
      voi[k] = __shfl_sync(0xffffffffu, vi, k, 8);
    }

    // M <- A(t) @ M : column update (256 FMA / thread / step).
    float nrr[8], nii[8];
    #pragma unroll
    for (int i = 0; i < 8; i++) {
      float sr2 = 0.f, si2 = 0.f;
      #pragma unroll
      for (int q = 0; q < 2; q++) {
        const float4 ar = sA[u][i * 2 + q];
        const float4 ai = sA[u][16 + i * 2 + q];
        const int k0 = q * 4;
        CMAC(sr2, si2, ar.x, ai.x, cr[k0 + 0], ci[k0 + 0]);
        CMAC(sr2, si2, ar.y, ai.y, cr[k0 + 1], ci[k0 + 1]);
        CMAC(sr2, si2, ar.z, ai.z, cr[k0 + 2], ci[k0 + 2]);
        CMAC(sr2, si2, ar.w, ai.w, cr[k0 + 3], ci[k0 + 3]);
      }
      nrr[i] = sr2; nii[i] = si2;
    }

    // v <- A(t) v + X(t) : row j.
    float svr = cxr, svi = cxi;
    #pragma unroll
    for (int q = 0; q < 2; q++) {
      const float4 ar = sA[u][j * 2 + q];
      const float4 ai = sA[u][16 + j * 2 + q];
      const int k0 = q * 4;
      CMAC(svr, svi, ar.x, ai.x, vor[k0 + 0], voi[k0 + 0]);
      CMAC(svr, svi, ar.y, ai.y, vor[k0 + 1], voi[k0 + 1]);
      CMAC(svr, svi, ar.z, ai.z, vor[k0 + 2], voi[k0 + 2]);
      CMAC(svr, svi, ar.w, ai.w, vor[k0 + 3], voi[k0 + 3]);
    }
    #pragma unroll
    for (int i = 0; i < 8; i++) { cr[i] = nrr[i]; ci[i] = nii[i]; }
    vr = svr; vi = svi;
  }

  // Store column j of M (row-major layout for kernel 2's row reads) and v[j].
  float2* gm = g_M2 + (size_t)unit * 64;
  #pragma unroll
  for (int i = 0; i < 8; i++) gm[i * 8 + j] = make_float2(cr[i], ci[i]);
  g_v2[unit * 8 + j] = make_float2(vr, vi);
}

// ---------------------------------------------------------------------------
// Kernel 2: serial scan over 32 chunks per sequence. 8 threads per sequence,
// thread i owns state element i. Stores entering state E per chunk.
// ---------------------------------------------------------------------------
__global__ void k_scan()
{
  const int gid = blockIdx.x * blockDim.x + threadIdx.x;
  const int seq = gid >> 3, i = gid & 7;
  if (seq >= NSEQ) return;
  float er = 0.f, ei = 0.f;   // state entering chunk 0 is zero => y0 = X0

  // Prefetch chunk 0 row i of M and v[i].
  const float4* mp = (const float4*)(g_M2 + (size_t)(seq * 32) * 64 + i * 8);
  float4 m0 = mp[0], m1 = mp[1], m2 = mp[2], m3 = mp[3];
  float2 vv = g_v2[(seq * 32) * 8 + i];

  for (int ch = 0; ch < NCHUNK; ++ch) {
    const int unit = seq * 32 + ch;
    g_E2[unit * 8 + i] = make_float2(er, ei);
    const float4 c0 = m0, c1 = m1, c2 = m2, c3 = m3;
    const float2 cv = vv;
    if (ch < NCHUNK - 1) {
      const float4* np = (const float4*)(g_M2 + (size_t)(unit + 1) * 64 + i * 8);
      m0 = np[0]; m1 = np[1]; m2 = np[2]; m3 = np[3];
      vv = g_v2[(unit + 1) * 8 + i];
    }
    float eor[8], eoi[8];
    #pragma unroll
    for (int k = 0; k < 8; k++) {
      eor[k] = __shfl_sync(0xffffffffu, er, k, 8);
      eoi[k] = __shfl_sync(0xffffffffu, ei, k, 8);
    }
    float sr = cv.x, si = cv.y;
    CMAC(sr, si, c0.x, c0.y, eor[0], eoi[0]);
    CMAC(sr, si, c0.z, c0.w, eor[1], eoi[1]);
    CMAC(sr, si, c1.x, c1.y, eor[2], eoi[2]);
    CMAC(sr, si, c1.z, c1.w, eor[3], eoi[3]);
    CMAC(sr, si, c2.x, c2.y, eor[4], eoi[4]);
    CMAC(sr, si, c2.z, c2.w, eor[5], eoi[5]);
    CMAC(sr, si, c3.x, c3.y, eor[6], eoi[6]);
    CMAC(sr, si, c3.z, c3.w, eor[7], eoi[7]);
    er = sr; ei = si;
  }
}

// ---------------------------------------------------------------------------
// Kernel 3: replay each chunk serially from its entering state, write Y.
// 8 threads per unit, thread j owns y[j] and reads row j of A (private,
// coalesced within the unit) — no SMEM needed.
// ---------------------------------------------------------------------------
__global__ __launch_bounds__(256) void k_replay(
    const float* __restrict__ Are, const float* __restrict__ Aim,
    const float* __restrict__ Xre, const float* __restrict__ Xim,
    float2* __restrict__ out)
{
  const int tid = threadIdx.x;
  const int u = tid >> 3, j = tid & 7;
  const int unit = blockIdx.x * 32 + u;
  const int seq = unit >> 5, chunk = unit & 31;
  const int b = seq >> 6, c = seq & 63;
  const int t0 = chunk * T;

  const float* arp = Are + (size_t)(b * Lc + t0) * 4096 + c * 64 + j * 8;
  const float* aip = Aim + (size_t)(b * Lc + t0) * 4096 + c * 64 + j * 8;
  const float* xrp = Xre + (size_t)(b * Lc + t0) * 512 + c * 8 + j;
  const float* xip = Xim + (size_t)(b * Lc + t0) * 512 + c * 8 + j;
  float2* op = out + (size_t)(b * Lc + t0) * 512 + c * 8 + j;

  float2 y = g_E2[unit * 8 + j];

  // Prefetch step t0.
  float4 r0 = *(const float4*)(arp), r1 = *(const float4*)(arp + 4);
  float4 i0 = *(const float4*)(aip), i1 = *(const float4*)(aip + 4);
  float xr = xrp[0], xi = xip[0];

  for (int s = 0; s < T; ++s) {
    const float4 cr0 = r0, cr1 = r1, ci0 = i0, ci1 = i1;
    const float cxr = xr, cxi = xi;
    if (s < T - 1) {   // prefetch next step while the y-chain computes
      arp += 4096; aip += 4096; xrp += 512; xip += 512;
      r0 = *(const float4*)(arp); r1 = *(const float4*)(arp + 4);
      i0 = *(const float4*)(aip); i1 = *(const float4*)(aip + 4);
      xr = xrp[0]; xi = xip[0];
    }
    float yor[8], yoi[8];
    #pragma unroll
    for (int k = 0; k < 8; k++) {
      yor[k] = __shfl_sync(0xffffffffu, y.x, k, 8);
      yoi[k] = __shfl_sync(0xffffffffu, y.y, k, 8);
    }
    float sr = cxr, si = cxi;
    CMAC(sr, si, cr0.x, ci0.x, yor[0], yoi[0]);
    CMAC(sr, si, cr0.y, ci0.y, yor[1], yoi[1]);
    CMAC(sr, si, cr0.z, ci0.z, yor[2], yoi[2]);
    CMAC(sr, si, cr0.w, ci0.w, yor[3], yoi[3]);
    CMAC(sr, si, cr1.x, ci1.x, yor[4], yoi[4]);
    CMAC(sr, si, cr1.y, ci1.y, yor[5], yoi[5]);
    CMAC(sr, si, cr1.z, ci1.z, yor[6], yoi[6]);
    CMAC(sr, si, cr1.w, ci1.w, yor[7], yoi[7]);
    y = make_float2(sr, si);
    *op = y;            // coalesced 64 B per unit per step
    op += 512;
  }
}

// ---------------------------------------------------------------------------
extern "C" void kernel_launch(void* const* d_in, const int* in_sizes, int n_in,
                              void* d_out, int out_size)
{
  const float* Are = (const float*)d_in[0];
  const float* Aim = (const float*)d_in[1];
  const float* Xre = (const float*)d_in[2];
  const float* Xim = (const float*)d_in[3];
  float2* out = (float2*)d_out;

  k_fold<<<NUNIT / 32, 256>>>(Are, Aim, Xre, Xim);
  k_scan<<<8, 256>>>();
  k_replay<<<NUNIT / 32, 256>>>(Are, Aim, Xre, Xim, out);
}